// round 3
// baseline (speedup 1.0000x reference)
#include <cuda_runtime.h>
#include <math.h>

// Problem constants
#define BATCH 4
#define SEQ   2048
#define DIM   1024

// Tiling
#define BM 128
#define BN 128
#define BK 16

// Scratch (device globals: allocation-free per harness rules)
__device__ float g_q[BATCH * SEQ * DIM];          // 32 MB
__device__ float g_k[BATCH * SEQ * DIM];          // 32 MB
__device__ float g_v[BATCH * SEQ * DIM];          // 32 MB
__device__ float g_s[(size_t)BATCH * SEQ * SEQ];  // 64 MB scores/weights

// ---------------------------------------------------------------------------
// Shared GEMM-NT body (A row-major [M,K], B row-major [N,K], C = A @ B^T).
// Software-pipelined: global->register prefetch of tile t+1 during compute
// of tile t. Both A and B tiles are K-major rows of length BK -> transposed
// into smem as [BK][128].
// ---------------------------------------------------------------------------
struct TileRegs { float4 a[2]; float4 b[2]; };

__device__ __forceinline__ void load_tiles_nt(
    TileRegs& r, const float* __restrict__ Ab, const float* __restrict__ Bb,
    int k0, int ldA, int ldB, int tid)
{
#pragma unroll
    for (int p = 0; p < 2; p++) {
        int f = tid + p * 256;           // 0..511
        int row = f >> 2;                // 0..127
        int c4  = (f & 3) * 4;           // 0,4,8,12
        r.a[p] = *(const float4*)(Ab + (size_t)row * ldA + k0 + c4);
        r.b[p] = *(const float4*)(Bb + (size_t)row * ldB + k0 + c4);
    }
}

__device__ __forceinline__ void commit_tiles_nt(
    const TileRegs& r, float As[BK][BM + 4], float Bs[BK][BN + 4], int tid)
{
#pragma unroll
    for (int p = 0; p < 2; p++) {
        int f = tid + p * 256;
        int row = f >> 2;
        int c4  = (f & 3) * 4;
        As[c4 + 0][row] = r.a[p].x; As[c4 + 1][row] = r.a[p].y;
        As[c4 + 2][row] = r.a[p].z; As[c4 + 3][row] = r.a[p].w;
        Bs[c4 + 0][row] = r.b[p].x; Bs[c4 + 1][row] = r.b[p].y;
        Bs[c4 + 2][row] = r.b[p].z; Bs[c4 + 3][row] = r.b[p].w;
    }
}

__device__ __forceinline__ void mma_tile(
    float acc[8][8], const float As[BK][BM + 4], const float Bs[BK][BN + 4],
    int tx, int ty)
{
#pragma unroll
    for (int kk = 0; kk < BK; kk++) {
        float ra[8], rb[8];
#pragma unroll
        for (int i = 0; i < 8; i++) ra[i] = As[kk][ty * 8 + i];
#pragma unroll
        for (int j = 0; j < 8; j++) rb[j] = Bs[kk][tx * 8 + j];
#pragma unroll
        for (int i = 0; i < 8; i++)
#pragma unroll
            for (int j = 0; j < 8; j++)
                acc[i][j] = fmaf(ra[i], rb[j], acc[i][j]);
    }
}

// ---------------------------------------------------------------------------
// QKV projection: C = X @ W^T  (NT GEMM), M=8192, N=1024, K=1024
// blockIdx.z selects {Wq,Wk,Wv} -> {g_q,g_k,g_v}
// ---------------------------------------------------------------------------
__global__ __launch_bounds__(256, 2) void qkv_kernel(
    const float* __restrict__ x, const float* __restrict__ Wq,
    const float* __restrict__ Wk, const float* __restrict__ Wv)
{
    __shared__ float As[BK][BM + 4];
    __shared__ float Bs[BK][BN + 4];

    const float* W   = (blockIdx.z == 0) ? Wq : (blockIdx.z == 1) ? Wk : Wv;
    float*       out = (blockIdx.z == 0) ? g_q : (blockIdx.z == 1) ? g_k : g_v;

    const int K = DIM;
    const float* Ab = x + (size_t)blockIdx.y * BM * K;
    const float* Bb = W + (size_t)blockIdx.x * BN * K;

    const int tid = threadIdx.x;
    const int tx = tid & 15, ty = tid >> 4;

    float acc[8][8];
#pragma unroll
    for (int i = 0; i < 8; i++)
#pragma unroll
        for (int j = 0; j < 8; j++) acc[i][j] = 0.f;

    TileRegs r;
    load_tiles_nt(r, Ab, Bb, 0, K, K, tid);

    for (int k0 = 0; k0 < K; k0 += BK) {
        commit_tiles_nt(r, As, Bs, tid);
        __syncthreads();
        if (k0 + BK < K)
            load_tiles_nt(r, Ab, Bb, k0 + BK, K, K, tid);
        mma_tile(acc, As, Bs, tx, ty);
        __syncthreads();
    }

    const int rowA = blockIdx.y * BM + ty * 8;
    const int colB = blockIdx.x * BN + tx * 8;
#pragma unroll
    for (int i = 0; i < 8; i++)
#pragma unroll
        for (int j = 0; j < 8; j++)
            out[(size_t)(rowA + i) * DIM + colB + j] = acc[i][j];
}

// ---------------------------------------------------------------------------
// Scores: S[b] = (Q[b] @ K[b]^T) * scale, causal -> only lower-tri blocks.
// Upper-tri entries are never read by softmax, so no masking needed.
// ---------------------------------------------------------------------------
__global__ __launch_bounds__(256, 2) void scores_kernel()
{
    if (blockIdx.x > blockIdx.y) return;   // fully above causal diagonal

    __shared__ float As[BK][BM + 4];
    __shared__ float Bs[BK][BN + 4];

    const int b = blockIdx.z;
    const int K = DIM;
    const float* Ab = g_q + (size_t)b * SEQ * DIM + (size_t)blockIdx.y * BM * K;
    const float* Bb = g_k + (size_t)b * SEQ * DIM + (size_t)blockIdx.x * BN * K;
    float*       S  = g_s + (size_t)b * SEQ * SEQ;

    const int tid = threadIdx.x;
    const int tx = tid & 15, ty = tid >> 4;

    float acc[8][8];
#pragma unroll
    for (int i = 0; i < 8; i++)
#pragma unroll
        for (int j = 0; j < 8; j++) acc[i][j] = 0.f;

    TileRegs r;
    load_tiles_nt(r, Ab, Bb, 0, K, K, tid);

    for (int k0 = 0; k0 < K; k0 += BK) {
        commit_tiles_nt(r, As, Bs, tid);
        __syncthreads();
        if (k0 + BK < K)
            load_tiles_nt(r, Ab, Bb, k0 + BK, K, K, tid);
        mma_tile(acc, As, Bs, tx, ty);
        __syncthreads();
    }

    const float scale = 0.03125f;  // 1/sqrt(1024)
    const int rowA = blockIdx.y * BM + ty * 8;
    const int colB = blockIdx.x * BN + tx * 8;
#pragma unroll
    for (int i = 0; i < 8; i++)
#pragma unroll
        for (int j = 0; j < 8; j++)
            S[(size_t)(rowA + i) * SEQ + colB + j] = acc[i][j] * scale;
}

// ---------------------------------------------------------------------------
// Causal row softmax: one block per row. Reads only j<=i, writes 0 for j>i.
// ---------------------------------------------------------------------------
__global__ __launch_bounds__(256) void softmax_kernel()
{
    const int row = blockIdx.x;          // 0..8191
    const int b = row >> 11;
    const int i = row & (SEQ - 1);
    float* p = g_s + (size_t)b * SEQ * SEQ + (size_t)i * SEQ;
    const int len = i + 1;
    const int tid = threadIdx.x;

    __shared__ float red[8];

    // --- max ---
    float m = -INFINITY;
    for (int j = tid; j < len; j += 256) m = fmaxf(m, p[j]);
#pragma unroll
    for (int o = 16; o; o >>= 1) m = fmaxf(m, __shfl_xor_sync(0xffffffffu, m, o));
    if ((tid & 31) == 0) red[tid >> 5] = m;
    __syncthreads();
    if (tid == 0) {
        float v = red[0];
#pragma unroll
        for (int w = 1; w < 8; w++) v = fmaxf(v, red[w]);
        red[0] = v;
    }
    __syncthreads();
    m = red[0];
    __syncthreads();

    // --- exp + sum ---
    float s = 0.f;
    for (int j = tid; j < len; j += 256) {
        float e = __expf(p[j] - m);
        p[j] = e;
        s += e;
    }
#pragma unroll
    for (int o = 16; o; o >>= 1) s += __shfl_xor_sync(0xffffffffu, s, o);
    if ((tid & 31) == 0) red[tid >> 5] = s;
    __syncthreads();
    if (tid == 0) {
        float v = red[0];
#pragma unroll
        for (int w = 1; w < 8; w++) v += red[w];
        red[0] = v;
    }
    __syncthreads();
    const float inv = 1.f / red[0];

    // --- normalize + zero the masked tail ---
    for (int j = tid; j < len; j += 256) p[j] *= inv;
    for (int j = len + tid; j < SEQ; j += 256) p[j] = 0.f;
}

// ---------------------------------------------------------------------------
// Output: O[b] = P[b] @ V[b]  (NN GEMM), M=2048, N=1024, K=2048
// K-loop truncated at causal boundary (weights beyond are zero).
// Pipelined like the NT kernels.
// ---------------------------------------------------------------------------
__global__ __launch_bounds__(256, 2) void out_kernel(float* __restrict__ O)
{
    __shared__ float As[BK][BM + 4];
    __shared__ float Bs[BK][BN + 4];

    const int b = blockIdx.z;
    const float* P = g_s + (size_t)b * SEQ * SEQ + (size_t)blockIdx.y * BM * SEQ;
    const float* V = g_v + (size_t)b * SEQ * DIM;

    const int tid = threadIdx.x;
    const int tx = tid & 15, ty = tid >> 4;
    const int ktiles = (blockIdx.y + 1) * (BM / BK);  // causal cut

    float acc[8][8];
#pragma unroll
    for (int i = 0; i < 8; i++)
#pragma unroll
        for (int j = 0; j < 8; j++) acc[i][j] = 0.f;

    // prefetch registers
    float4 pa[2], pb[2];
    {
        const int k0 = 0;
#pragma unroll
        for (int p = 0; p < 2; p++) {
            int f = tid + p * 256;
            int row = f >> 2;
            int c4  = (f & 3) * 4;
            pa[p] = *(const float4*)(P + (size_t)row * SEQ + k0 + c4);
            int rowv = f >> 5;
            int co   = (f & 31) * 4;
            pb[p] = *(const float4*)(V + (size_t)(k0 + rowv) * DIM +
                                     blockIdx.x * BN + co);
        }
    }

    for (int t = 0; t < ktiles; t++) {
        // commit prefetched tile to smem
#pragma unroll
        for (int p = 0; p < 2; p++) {
            int f = tid + p * 256;
            int row = f >> 2;
            int c4  = (f & 3) * 4;
            As[c4 + 0][row] = pa[p].x; As[c4 + 1][row] = pa[p].y;
            As[c4 + 2][row] = pa[p].z; As[c4 + 3][row] = pa[p].w;
            int rowv = f >> 5;
            int co   = (f & 31) * 4;
            *(float4*)&Bs[rowv][co] = pb[p];
        }
        __syncthreads();

        if (t + 1 < ktiles) {
            const int k0 = (t + 1) * BK;
#pragma unroll
            for (int p = 0; p < 2; p++) {
                int f = tid + p * 256;
                int row = f >> 2;
                int c4  = (f & 3) * 4;
                pa[p] = *(const float4*)(P + (size_t)row * SEQ + k0 + c4);
                int rowv = f >> 5;
                int co   = (f & 31) * 4;
                pb[p] = *(const float4*)(V + (size_t)(k0 + rowv) * DIM +
                                         blockIdx.x * BN + co);
            }
        }

        mma_tile(acc, As, Bs, tx, ty);
        __syncthreads();
    }

    const int rowA = blockIdx.y * BM + ty * 8;
    const int colB = blockIdx.x * BN + tx * 8;
    float* Ob = O + (size_t)b * SEQ * DIM;
#pragma unroll
    for (int i = 0; i < 8; i++)
#pragma unroll
        for (int j = 0; j < 8; j++)
            Ob[(size_t)(rowA + i) * DIM + colB + j] = acc[i][j];
}

// ---------------------------------------------------------------------------
extern "C" void kernel_launch(void* const* d_in, const int* in_sizes, int n_in,
                              void* d_out, int out_size)
{
    const float* x  = (const float*)d_in[0];
    const float* Wq = (const float*)d_in[1];
    const float* Wk = (const float*)d_in[2];
    const float* Wv = (const float*)d_in[3];
    float* out = (float*)d_out;

    qkv_kernel<<<dim3(DIM / BN, (BATCH * SEQ) / BM, 3), 256>>>(x, Wq, Wk, Wv);
    scores_kernel<<<dim3(SEQ / BN, SEQ / BM, BATCH), 256>>>();
    softmax_kernel<<<BATCH * SEQ, 256>>>();
    out_kernel<<<dim3(DIM / BN, SEQ / BM, BATCH), 256>>>(out);
}

// round 7
// speedup vs baseline: 1.3133x; 1.3133x over previous
#include <cuda_runtime.h>
#include <mma.h>
#include <cstdint>
#include <math.h>

using namespace nvcuda;

// Problem constants
#define BATCH 4
#define SEQ   2048
#define DIM   1024

// Tile config
#define BK      32
#define LDS     40          // smem row stride in floats (mult of 4, +8 skew)
#define WM      64          // warp tile M (4 x 16)
#define WN      32          // warp tile N (2 x 16)

// Scratch (device globals: allocation-free per harness rules)
__device__ float g_q[BATCH * SEQ * DIM];          // Q   [B][SEQ][DIM]
__device__ float g_k[BATCH * SEQ * DIM];          // K   [B][SEQ][DIM]
__device__ float g_v[BATCH * SEQ * DIM];          // V^T [B][DIM][SEQ] (transposed)
__device__ float g_s[(size_t)BATCH * SEQ * SEQ];  // scores / weights

typedef wmma::fragment<wmma::matrix_a, 16, 16, 8, wmma::precision::tf32, wmma::row_major> FragA;
typedef wmma::fragment<wmma::matrix_b, 16, 16, 8, wmma::precision::tf32, wmma::col_major> FragB;
typedef wmma::fragment<wmma::accumulator, 16, 16, 8, float> FragC;

// ---------------------------------------------------------------------------
// Cooperative load of one 128xBK f32 tile into smem (row stride LDS).
// ---------------------------------------------------------------------------
__device__ __forceinline__ void load_tile(
    float* __restrict__ S, const float* __restrict__ G, long ldg, int k0, int tid)
{
#pragma unroll
    for (int p = 0; p < 4; p++) {
        int f   = tid + p * 256;            // 0..1023
        int row = f >> 3;                   // 0..127
        int c4  = (f & 7) << 2;             // 0,4,...,28
        float4 v = *(const float4*)(G + (size_t)row * ldg + k0 + c4);
        *(float4*)(S + row * LDS + c4) = v;
    }
}

// ---------------------------------------------------------------------------
// Warp-level mainloop body over one BK chunk already resident in smem.
// fc[4][2] accumulators; warp at (wm0, wn0) within the 128x128 tile.
// ---------------------------------------------------------------------------
__device__ __forceinline__ void mma_chunk(
    FragC fc[4][2], const float* __restrict__ As, const float* __restrict__ Bs,
    int wm0, int wn0)
{
#pragma unroll
    for (int ks = 0; ks < BK / 8; ks++) {
        const int k0 = ks * 8;
        FragA fa[4];
        FragB fb[2];
#pragma unroll
        for (int mm = 0; mm < 4; mm++) {
            wmma::load_matrix_sync(fa[mm], As + (wm0 + mm * 16) * LDS + k0, LDS);
#pragma unroll
            for (int e = 0; e < fa[mm].num_elements; e++)
                fa[mm].x[e] = wmma::__float_to_tf32(fa[mm].x[e]);
        }
#pragma unroll
        for (int nn = 0; nn < 2; nn++) {
            wmma::load_matrix_sync(fb[nn], Bs + (wn0 + nn * 16) * LDS + k0, LDS);
#pragma unroll
            for (int e = 0; e < fb[nn].num_elements; e++)
                fb[nn].x[e] = wmma::__float_to_tf32(fb[nn].x[e]);
        }
#pragma unroll
        for (int mm = 0; mm < 4; mm++)
#pragma unroll
            for (int nn = 0; nn < 2; nn++)
                wmma::mma_sync(fc[mm][nn], fa[mm], fb[nn], fc[mm][nn]);
    }
}

// ===========================================================================
// QKV: C = X @ W^T (NT), M=8192, N=1024, K=1024. z: 0=Q, 1=K, 2=V(->V^T)
// ===========================================================================
__global__ __launch_bounds__(256) void qkv_kernel(
    const float* __restrict__ x, const float* __restrict__ Wq,
    const float* __restrict__ Wk, const float* __restrict__ Wv)
{
    __shared__ float As[128 * LDS];
    __shared__ float Bs[128 * LDS];

    const int tid = threadIdx.x, wid = tid >> 5;
    const int wm0 = (wid >> 2) * WM;     // 0 or 64
    const int wn0 = (wid & 3) * WN;      // 0,32,64,96
    const int z = blockIdx.z;

    const float* W  = (z == 0) ? Wq : (z == 1) ? Wk : Wv;
    const float* Ab = x + (size_t)blockIdx.y * 128 * DIM;
    const float* Bb = W + (size_t)blockIdx.x * 128 * DIM;

    FragC fc[4][2];
#pragma unroll
    for (int mm = 0; mm < 4; mm++)
#pragma unroll
        for (int nn = 0; nn < 2; nn++) wmma::fill_fragment(fc[mm][nn], 0.f);

    for (int k0 = 0; k0 < DIM; k0 += BK) {
        load_tile(As, Ab, DIM, k0, tid);
        load_tile(Bs, Bb, DIM, k0, tid);
        __syncthreads();
        mma_chunk(fc, As, Bs, wm0, wn0);
        __syncthreads();
    }

    if (z < 2) {
        float* C = (z ? g_k : g_q);
        const int row0 = blockIdx.y * 128 + wm0;
        const int col0 = blockIdx.x * 128 + wn0;
#pragma unroll
        for (int mm = 0; mm < 4; mm++)
#pragma unroll
            for (int nn = 0; nn < 2; nn++)
                wmma::store_matrix_sync(
                    C + (size_t)(row0 + mm * 16) * DIM + col0 + nn * 16,
                    fc[mm][nn], DIM, wmma::mem_row_major);
    } else {
        // V^T: store accumulator col-major -> vt[dim][token]
        const int row_g = blockIdx.y * 128;          // global token base
        const int b     = row_g >> 11;
        const int tok0  = (row_g & (SEQ - 1)) + wm0;
        const int dim0  = blockIdx.x * 128 + wn0;
        float* vt = g_v + (size_t)b * DIM * SEQ;
#pragma unroll
        for (int mm = 0; mm < 4; mm++)
#pragma unroll
            for (int nn = 0; nn < 2; nn++)
                wmma::store_matrix_sync(
                    vt + (size_t)(dim0 + nn * 16) * SEQ + tok0 + mm * 16,
                    fc[mm][nn], SEQ, wmma::mem_col_major);
    }
}

// ===========================================================================
// Scores: S = (Q @ K^T) * scale, lower-triangular 128x128 blocks only
// ===========================================================================
__global__ __launch_bounds__(256) void scores_kernel()
{
    if (blockIdx.x > blockIdx.y) return;     // above causal diagonal

    __shared__ float As[128 * LDS];
    __shared__ float Bs[128 * LDS];

    const int tid = threadIdx.x, wid = tid >> 5;
    const int wm0 = (wid >> 2) * WM;
    const int wn0 = (wid & 3) * WN;
    const int b = blockIdx.z;

    const float* Ab = g_q + ((size_t)b * SEQ + blockIdx.y * 128) * DIM;
    const float* Bb = g_k + ((size_t)b * SEQ + blockIdx.x * 128) * DIM;

    FragC fc[4][2];
#pragma unroll
    for (int mm = 0; mm < 4; mm++)
#pragma unroll
        for (int nn = 0; nn < 2; nn++) wmma::fill_fragment(fc[mm][nn], 0.f);

    for (int k0 = 0; k0 < DIM; k0 += BK) {
        load_tile(As, Ab, DIM, k0, tid);
        load_tile(Bs, Bb, DIM, k0, tid);
        __syncthreads();
        mma_chunk(fc, As, Bs, wm0, wn0);
        __syncthreads();
    }

    float* S = g_s + (size_t)b * SEQ * SEQ;
    const int row0 = blockIdx.y * 128 + wm0;
    const int col0 = blockIdx.x * 128 + wn0;
#pragma unroll
    for (int mm = 0; mm < 4; mm++)
#pragma unroll
        for (int nn = 0; nn < 2; nn++) {
#pragma unroll
            for (int e = 0; e < fc[mm][nn].num_elements; e++)
                fc[mm][nn].x[e] *= 0.03125f;     // 1/sqrt(1024)
            wmma::store_matrix_sync(
                S + (size_t)(row0 + mm * 16) * SEQ + col0 + nn * 16,
                fc[mm][nn], SEQ, wmma::mem_row_major);
        }
}

// ===========================================================================
// Output: O = P @ V = P @ (V^T)^T -> NT GEMM against g_v, causal K-cut
// ===========================================================================
__global__ __launch_bounds__(256) void out_kernel(float* __restrict__ O)
{
    __shared__ float As[128 * LDS];
    __shared__ float Bs[128 * LDS];

    const int tid = threadIdx.x, wid = tid >> 5;
    const int wm0 = (wid >> 2) * WM;
    const int wn0 = (wid & 3) * WN;
    const int b = blockIdx.z;

    const float* Ab = g_s + (size_t)b * SEQ * SEQ + (size_t)blockIdx.y * 128 * SEQ;
    const float* Bb = g_v + (size_t)b * DIM * SEQ + (size_t)blockIdx.x * 128 * SEQ;
    const int kend = (blockIdx.y + 1) * 128;     // causal cut

    FragC fc[4][2];
#pragma unroll
    for (int mm = 0; mm < 4; mm++)
#pragma unroll
        for (int nn = 0; nn < 2; nn++) wmma::fill_fragment(fc[mm][nn], 0.f);

    for (int k0 = 0; k0 < kend; k0 += BK) {
        load_tile(As, Ab, SEQ, k0, tid);
        load_tile(Bs, Bb, SEQ, k0, tid);
        __syncthreads();
        mma_chunk(fc, As, Bs, wm0, wn0);
        __syncthreads();
    }

    float* Ob = O + (size_t)b * SEQ * DIM;
    const int row0 = blockIdx.y * 128 + wm0;
    const int col0 = blockIdx.x * 128 + wn0;
#pragma unroll
    for (int mm = 0; mm < 4; mm++)
#pragma unroll
        for (int nn = 0; nn < 2; nn++)
            wmma::store_matrix_sync(
                Ob + (size_t)(row0 + mm * 16) * DIM + col0 + nn * 16,
                fc[mm][nn], DIM, wmma::mem_row_major);
}

// ===========================================================================
// Causal row softmax (unchanged from passing R3 kernel)
// ===========================================================================
__global__ __launch_bounds__(256) void softmax_kernel()
{
    const int row = blockIdx.x;
    const int b = row >> 11;
    const int i = row & (SEQ - 1);
    float* p = g_s + (size_t)b * SEQ * SEQ + (size_t)i * SEQ;
    const int len = i + 1;
    const int tid = threadIdx.x;

    __shared__ float red[8];

    float m = -INFINITY;
    for (int j = tid; j < len; j += 256) m = fmaxf(m, p[j]);
#pragma unroll
    for (int o = 16; o; o >>= 1) m = fmaxf(m, __shfl_xor_sync(0xffffffffu, m, o));
    if ((tid & 31) == 0) red[tid >> 5] = m;
    __syncthreads();
    if (tid == 0) {
        float v = red[0];
#pragma unroll
        for (int w = 1; w < 8; w++) v = fmaxf(v, red[w]);
        red[0] = v;
    }
    __syncthreads();
    m = red[0];
    __syncthreads();

    float s = 0.f;
    for (int j = tid; j < len; j += 256) {
        float e = __expf(p[j] - m);
        p[j] = e;
        s += e;
    }
#pragma unroll
    for (int o = 16; o; o >>= 1) s += __shfl_xor_sync(0xffffffffu, s, o);
    if ((tid & 31) == 0) red[tid >> 5] = s;
    __syncthreads();
    if (tid == 0) {
        float v = red[0];
#pragma unroll
        for (int w = 1; w < 8; w++) v += red[w];
        red[0] = v;
    }
    __syncthreads();
    const float inv = 1.f / red[0];

    for (int j = tid; j < len; j += 256) p[j] *= inv;
    for (int j = len + tid; j < SEQ; j += 256) p[j] = 0.f;
}

// ===========================================================================
extern "C" void kernel_launch(void* const* d_in, const int* in_sizes, int n_in,
                              void* d_out, int out_size)
{
    const float* x  = (const float*)d_in[0];
    const float* Wq = (const float*)d_in[1];
    const float* Wk = (const float*)d_in[2];
    const float* Wv = (const float*)d_in[3];
    float* out = (float*)d_out;

    qkv_kernel<<<dim3(DIM / 128, (BATCH * SEQ) / 128, 3), 256>>>(x, Wq, Wk, Wv);
    scores_kernel<<<dim3(SEQ / 128, SEQ / 128, BATCH), 256>>>();
    softmax_kernel<<<BATCH * SEQ, 256>>>();
    out_kernel<<<dim3(DIM / 128, SEQ / 128, BATCH), 256>>>(out);
}